// round 1
// baseline (speedup 1.0000x reference)
// 2-layer GRU (H=32, B=4096, T=512) + 16-dim projection, fully fused.
// One warp handles NB=4 batch elements; lane = hidden unit index.
// h0/h1 in registers, weights transposed in shared (conflict-free),
// x/h broadcast via warp shuffle. Both layers fused per timestep -> no
// intermediate [B,T,H] tensor ever touches memory.
#include <cuda_runtime.h>

#define Hh 32
#define Tt 512
#define Bb 4096
#define NB 4                 // batch elements per warp
#define NWARP 2              // warps per block
#define NTHREADS (NWARP * 32)
#define NBLOCKS (Bb / (NB * NWARP))   // 512

__device__ __forceinline__ float fsig(float x) {
    return 1.0f / (1.0f + __expf(-x));
}
__device__ __forceinline__ float ftanh(float x) {
    // tanh(x) = 2*sigmoid(2x) - 1  (accurate to ~1e-6 rel with __expf)
    return fmaf(2.0f, fsig(2.0f * x), -1.0f);
}

__global__ void __launch_bounds__(NTHREADS) gru_fused_kernel(
    const float* __restrict__ x,
    const float* __restrict__ Wih0, const float* __restrict__ Whh0,
    const float* __restrict__ bih0, const float* __restrict__ bhh0,
    const float* __restrict__ Wih1, const float* __restrict__ Whh1,
    const float* __restrict__ bih1, const float* __restrict__ bhh1,
    const float* __restrict__ Wproj, const float* __restrict__ bproj,
    float* __restrict__ out)
{
    // 4 transposed weight matrices: Wt[k][j] = W[j][k], j = gate*32 + lane.
    // 4 * 32*96 floats = 49152 bytes = exactly 48KB static shared.
    __shared__ float sm[4 * 32 * 96];
    float* w0x = sm;            // layer0 W_ih^T
    float* w0h = sm + 3072;     // layer0 W_hh^T
    float* w1x = sm + 6144;     // layer1 W_ih^T
    float* w1h = sm + 9216;     // layer1 W_hh^T

    for (int idx = threadIdx.x; idx < 96 * 32; idx += NTHREADS) {
        const int j = idx >> 5;       // row (gate*32+i) in original [96][32]
        const int k = idx & 31;       // col (hidden k)
        const int d = k * 96 + j;     // transposed
        w0x[d] = Wih0[idx];
        w0h[d] = Whh0[idx];
        w1x[d] = Wih1[idx];
        w1h[d] = Whh1[idx];
    }
    __syncthreads();

    const int lane = threadIdx.x & 31;
    const int warp = blockIdx.x * NWARP + (threadIdx.x >> 5);
    const int b0   = warp * NB;

    // Per-lane gate biases (r/z: b_ih+b_hh folded; n: keep input/hidden split
    // because r multiplies only the hidden part).
    const float b0r  = bih0[lane]      + bhh0[lane];
    const float b0z  = bih0[32 + lane] + bhh0[32 + lane];
    const float b0xn = bih0[64 + lane];
    const float b0hn = bhh0[64 + lane];
    const float b1r  = bih1[lane]      + bhh1[lane];
    const float b1z  = bih1[32 + lane] + bhh1[32 + lane];
    const float b1xn = bih1[64 + lane];
    const float b1hn = bhh1[64 + lane];

    const float* xp[NB];
#pragma unroll
    for (int b = 0; b < NB; b++)
        xp[b] = x + (size_t)(b0 + b) * (Tt * Hh) + lane;

    float h0[NB], h1[NB], xv[NB];
#pragma unroll
    for (int b = 0; b < NB; b++) {
        h0[b] = 0.0f;
        h1[b] = 0.0f;
        xv[b] = xp[b][0];
        xp[b] += Hh;
    }

    for (int t = 0; t < Tt; t++) {
        // Prefetch next timestep's input while we compute this one.
        float xnext[NB];
        if (t + 1 < Tt) {
#pragma unroll
            for (int b = 0; b < NB; b++) { xnext[b] = xp[b][0]; xp[b] += Hh; }
        } else {
#pragma unroll
            for (int b = 0; b < NB; b++) xnext[b] = 0.0f;
        }

        // ================= layer 0 =================
        float ar[NB], az[NB], axn[NB], ahn[NB];
#pragma unroll
        for (int b = 0; b < NB; b++) {
            ar[b] = b0r; az[b] = b0z; axn[b] = b0xn; ahn[b] = b0hn;
        }
#pragma unroll
        for (int k = 0; k < 32; k++) {
            const float wr = w0x[k * 96 + lane];
            const float wz = w0x[k * 96 + 32 + lane];
            const float wn = w0x[k * 96 + 64 + lane];
#pragma unroll
            for (int b = 0; b < NB; b++) {
                const float v = __shfl_sync(0xffffffffu, xv[b], k);
                ar[b]  = fmaf(v, wr, ar[b]);
                az[b]  = fmaf(v, wz, az[b]);
                axn[b] = fmaf(v, wn, axn[b]);
            }
        }
#pragma unroll
        for (int k = 0; k < 32; k++) {
            const float wr = w0h[k * 96 + lane];
            const float wz = w0h[k * 96 + 32 + lane];
            const float wn = w0h[k * 96 + 64 + lane];
#pragma unroll
            for (int b = 0; b < NB; b++) {
                const float v = __shfl_sync(0xffffffffu, h0[b], k);
                ar[b]  = fmaf(v, wr, ar[b]);
                az[b]  = fmaf(v, wz, az[b]);
                ahn[b] = fmaf(v, wn, ahn[b]);
            }
        }
#pragma unroll
        for (int b = 0; b < NB; b++) {
            const float r  = fsig(ar[b]);
            const float z  = fsig(az[b]);
            const float nn = ftanh(fmaf(r, ahn[b], axn[b]));
            h0[b] = fmaf(z, h0[b] - nn, nn);      // (1-z)*n + z*h
        }

        // ================= layer 1 (input = fresh h0) =================
#pragma unroll
        for (int b = 0; b < NB; b++) {
            ar[b] = b1r; az[b] = b1z; axn[b] = b1xn; ahn[b] = b1hn;
        }
#pragma unroll
        for (int k = 0; k < 32; k++) {
            const float wr = w1x[k * 96 + lane];
            const float wz = w1x[k * 96 + 32 + lane];
            const float wn = w1x[k * 96 + 64 + lane];
#pragma unroll
            for (int b = 0; b < NB; b++) {
                const float v = __shfl_sync(0xffffffffu, h0[b], k);
                ar[b]  = fmaf(v, wr, ar[b]);
                az[b]  = fmaf(v, wz, az[b]);
                axn[b] = fmaf(v, wn, axn[b]);
            }
        }
#pragma unroll
        for (int k = 0; k < 32; k++) {
            const float wr = w1h[k * 96 + lane];
            const float wz = w1h[k * 96 + 32 + lane];
            const float wn = w1h[k * 96 + 64 + lane];
#pragma unroll
            for (int b = 0; b < NB; b++) {
                const float v = __shfl_sync(0xffffffffu, h1[b], k);
                ar[b]  = fmaf(v, wr, ar[b]);
                az[b]  = fmaf(v, wz, az[b]);
                ahn[b] = fmaf(v, wn, ahn[b]);
            }
        }
#pragma unroll
        for (int b = 0; b < NB; b++) {
            const float r  = fsig(ar[b]);
            const float z  = fsig(az[b]);
            const float nn = ftanh(fmaf(r, ahn[b], axn[b]));
            h1[b] = fmaf(z, h1[b] - nn, nn);
        }

#pragma unroll
        for (int b = 0; b < NB; b++) xv[b] = xnext[b];
    }

    // ============ projection: out[b] = h1 @ Wproj^T + bproj  (16 outputs) ============
#pragma unroll
    for (int b = 0; b < NB; b++) {
        float acc = (lane < 16) ? bproj[lane] : 0.0f;
#pragma unroll
        for (int k = 0; k < 32; k++) {
            const float v = __shfl_sync(0xffffffffu, h1[b], k);
            if (lane < 16) acc = fmaf(v, Wproj[lane * 32 + k], acc);
        }
        if (lane < 16) out[(b0 + b) * 16 + lane] = acc;
    }
}

extern "C" void kernel_launch(void* const* d_in, const int* in_sizes, int n_in,
                              void* d_out, int out_size)
{
    const float* x     = (const float*)d_in[0];
    const float* Wih0  = (const float*)d_in[1];
    const float* Whh0  = (const float*)d_in[2];
    const float* bih0  = (const float*)d_in[3];
    const float* bhh0  = (const float*)d_in[4];
    const float* Wih1  = (const float*)d_in[5];
    const float* Whh1  = (const float*)d_in[6];
    const float* bih1  = (const float*)d_in[7];
    const float* bhh1  = (const float*)d_in[8];
    const float* Wproj = (const float*)d_in[9];
    const float* bproj = (const float*)d_in[10];
    float* out = (float*)d_out;

    gru_fused_kernel<<<NBLOCKS, NTHREADS>>>(
        x, Wih0, Whh0, bih0, bhh0, Wih1, Whh1, bih1, bhh1, Wproj, bproj, out);
}

// round 2
// speedup vs baseline: 1.3039x; 1.3039x over previous
// 2-layer GRU (H=32, B=4096, T=512) + 16-dim projection, fully fused.
// Round 2: k-paired fma.rn.f32x2 (FFMA2), per-lane weight rows via
// conflict-free LDS.128 (stride-100 padding), x/h broadcast via shared
// staging (LDS.128 broadcast) -- zero shuffles in the hot loop.
#include <cuda_runtime.h>

#define Hh 32
#define Tt 512
#define Bb 4096
#define NB 4                      // batch elements per warp
#define NWARP 2                   // warps per block
#define NTHREADS (NWARP * 32)
#define NBLOCKS (Bb / (NB * NWARP))   // 512

#define WSTRIDE 100               // floats per (matrix,lane) row group (3*32 + 4 pad)
#define W_FLOATS (4 * 32 * WSTRIDE)          // 12800
#define STAGE_FLOATS (NWARP * 3 * NB * 32)   // 768
#define SMEM_BYTES ((W_FLOATS + STAGE_FLOATS) * 4)   // 54272

union F2 {
    float2 f;
    unsigned long long u;
};

__device__ __forceinline__ F2 mkF2(float x, float y) {
    F2 r; r.f.x = x; r.f.y = y; return r;
}

// d = a * b + d  (packed 2x fp32)
__device__ __forceinline__ void fma2(F2& d, F2 a, F2 b) {
    asm("fma.rn.f32x2 %0, %1, %2, %0;" : "+l"(d.u) : "l"(a.u), "l"(b.u));
}

__device__ __forceinline__ float fsig(float x) {
    return 1.0f / (1.0f + __expf(-x));
}
__device__ __forceinline__ float ftanh(float x) {
    return fmaf(2.0f, fsig(2.0f * x), -1.0f);
}

// One [32 -> 96] GEMV slice for NB batch elements.
// wrow: this lane's row group (gate r at +0, z at +32, n at +64), k-major.
// vsh:  staged broadcast operand, NB rows of 32 floats.
// Accumulates into f32x2 partial sums (even/odd k).
__device__ __forceinline__ void gemv96(const float* __restrict__ wrow,
                                       const float* __restrict__ vsh,
                                       F2* ar, F2* az, F2* an)
{
#pragma unroll
    for (int it = 0; it < 8; it++) {
        const float4 wr = *(const float4*)(wrow +       it * 4);
        const float4 wz = *(const float4*)(wrow + 32 +  it * 4);
        const float4 wn = *(const float4*)(wrow + 64 +  it * 4);
        const F2 wrl = mkF2(wr.x, wr.y), wrh = mkF2(wr.z, wr.w);
        const F2 wzl = mkF2(wz.x, wz.y), wzh = mkF2(wz.z, wz.w);
        const F2 wnl = mkF2(wn.x, wn.y), wnh = mkF2(wn.z, wn.w);
#pragma unroll
        for (int b = 0; b < NB; b++) {
            const float4 v = *(const float4*)(vsh + b * 32 + it * 4);  // broadcast
            const F2 vl = mkF2(v.x, v.y), vh = mkF2(v.z, v.w);
            fma2(ar[b], vl, wrl); fma2(ar[b], vh, wrh);
            fma2(az[b], vl, wzl); fma2(az[b], vh, wzh);
            fma2(an[b], vl, wnl); fma2(an[b], vh, wnh);
        }
    }
}

__global__ void __launch_bounds__(NTHREADS) gru_fused_kernel(
    const float* __restrict__ x,
    const float* __restrict__ Wih0, const float* __restrict__ Whh0,
    const float* __restrict__ bih0, const float* __restrict__ bhh0,
    const float* __restrict__ Wih1, const float* __restrict__ Whh1,
    const float* __restrict__ bih1, const float* __restrict__ bhh1,
    const float* __restrict__ Wproj, const float* __restrict__ bproj,
    float* __restrict__ out)
{
    extern __shared__ float sm[];
    float* wsm = sm;                              // 4 matrices, per-lane rows
    float* stage_base = sm + W_FLOATS;

    // ---- load weights: wsm[(m*32+i)*WSTRIDE + g*32 + k] = W_m[g*32+i][k] ----
    {
        const float* Ws[4] = {Wih0, Whh0, Wih1, Whh1};
#pragma unroll
        for (int m = 0; m < 4; m++) {
            const float* W = Ws[m];
            for (int idx = threadIdx.x; idx < 96 * 32; idx += NTHREADS) {
                const int j = idx >> 5;       // row in [96][32]
                const int k = idx & 31;
                const int g = j >> 5;         // gate 0..2
                const int i = j & 31;         // lane that owns this row
                wsm[(m * 32 + i) * WSTRIDE + g * 32 + k] = W[idx];
            }
        }
    }
    __syncthreads();

    const int lane  = threadIdx.x & 31;
    const int winb  = threadIdx.x >> 5;
    const int warp  = blockIdx.x * NWARP + winb;
    const int b0    = warp * NB;

    // this lane's weight row groups
    const float* w0x = wsm + (0 * 32 + lane) * WSTRIDE;
    const float* w0h = wsm + (1 * 32 + lane) * WSTRIDE;
    const float* w1x = wsm + (2 * 32 + lane) * WSTRIDE;
    const float* w1h = wsm + (3 * 32 + lane) * WSTRIDE;

    // per-warp staging: x_sh, h0_sh, h1_sh (NB x 32 each)
    float* stg   = stage_base + winb * (3 * NB * 32);
    float* x_sh  = stg;
    float* h0_sh = stg + NB * 32;
    float* h1_sh = stg + 2 * NB * 32;

    // biases, pre-packed: sum goes into .x partial
    const F2 b0r  = mkF2(bih0[lane]      + bhh0[lane],      0.0f);
    const F2 b0z  = mkF2(bih0[32 + lane] + bhh0[32 + lane], 0.0f);
    const F2 b0xn = mkF2(bih0[64 + lane], 0.0f);
    const F2 b0hn = mkF2(bhh0[64 + lane], 0.0f);
    const F2 b1r  = mkF2(bih1[lane]      + bhh1[lane],      0.0f);
    const F2 b1z  = mkF2(bih1[32 + lane] + bhh1[32 + lane], 0.0f);
    const F2 b1xn = mkF2(bih1[64 + lane], 0.0f);
    const F2 b1hn = mkF2(bhh1[64 + lane], 0.0f);

    const float* xp[NB];
#pragma unroll
    for (int b = 0; b < NB; b++)
        xp[b] = x + (size_t)(b0 + b) * (Tt * Hh) + lane;

    float h0[NB], h1[NB];
#pragma unroll
    for (int b = 0; b < NB; b++) {
        h0[b] = 0.0f;
        h1[b] = 0.0f;
        x_sh [b * 32 + lane] = xp[b][0];
        h0_sh[b * 32 + lane] = 0.0f;
        h1_sh[b * 32 + lane] = 0.0f;
        xp[b] += Hh;
    }
    __syncwarp();

    for (int t = 0; t < Tt; t++) {
        // prefetch next x into registers
        float xn[NB];
        if (t + 1 < Tt) {
#pragma unroll
            for (int b = 0; b < NB; b++) { xn[b] = xp[b][0]; xp[b] += Hh; }
        } else {
#pragma unroll
            for (int b = 0; b < NB; b++) xn[b] = 0.0f;
        }

        // ================= layer 0 =================
        F2 ar[NB], az[NB], axn[NB], ahn[NB];
#pragma unroll
        for (int b = 0; b < NB; b++) { ar[b] = b0r; az[b] = b0z; axn[b] = b0xn; ahn[b] = b0hn; }

        gemv96(w0x, x_sh,  ar, az, axn);
        gemv96(w0h, h0_sh, ar, az, ahn);

        float h0new[NB];
#pragma unroll
        for (int b = 0; b < NB; b++) {
            const float r  = fsig(ar[b].f.x + ar[b].f.y);
            const float z  = fsig(az[b].f.x + az[b].f.y);
            const float nn = ftanh(fmaf(r, ahn[b].f.x + ahn[b].f.y,
                                           axn[b].f.x + axn[b].f.y));
            h0new[b] = fmaf(z, h0[b] - nn, nn);     // (1-z)*n + z*h
        }
        __syncwarp();                                // all lanes done reading x_sh/h0_sh
#pragma unroll
        for (int b = 0; b < NB; b++) {
            h0_sh[b * 32 + lane] = h0new[b];
            x_sh [b * 32 + lane] = xn[b];            // stage next timestep's x
            h0[b] = h0new[b];
        }
        __syncwarp();

        // ================= layer 1 (input = fresh h0) =================
#pragma unroll
        for (int b = 0; b < NB; b++) { ar[b] = b1r; az[b] = b1z; axn[b] = b1xn; ahn[b] = b1hn; }

        gemv96(w1x, h0_sh, ar, az, axn);
        gemv96(w1h, h1_sh, ar, az, ahn);

        float h1new[NB];
#pragma unroll
        for (int b = 0; b < NB; b++) {
            const float r  = fsig(ar[b].f.x + ar[b].f.y);
            const float z  = fsig(az[b].f.x + az[b].f.y);
            const float nn = ftanh(fmaf(r, ahn[b].f.x + ahn[b].f.y,
                                           axn[b].f.x + axn[b].f.y));
            h1new[b] = fmaf(z, h1[b] - nn, nn);
        }
        __syncwarp();
#pragma unroll
        for (int b = 0; b < NB; b++) {
            h1_sh[b * 32 + lane] = h1new[b];
            h1[b] = h1new[b];
        }
        __syncwarp();
    }

    // ============ projection: out[b] = h1 @ Wproj^T + bproj ============
#pragma unroll
    for (int b = 0; b < NB; b++) {
        float acc = (lane < 16) ? bproj[lane] : 0.0f;
#pragma unroll
        for (int k = 0; k < 32; k++) {
            const float v = __shfl_sync(0xffffffffu, h1[b], k);
            if (lane < 16) acc = fmaf(v, Wproj[lane * 32 + k], acc);
        }
        if (lane < 16) out[(b0 + b) * 16 + lane] = acc;
    }
}

extern "C" void kernel_launch(void* const* d_in, const int* in_sizes, int n_in,
                              void* d_out, int out_size)
{
    const float* x     = (const float*)d_in[0];
    const float* Wih0  = (const float*)d_in[1];
    const float* Whh0  = (const float*)d_in[2];
    const float* bih0  = (const float*)d_in[3];
    const float* bhh0  = (const float*)d_in[4];
    const float* Wih1  = (const float*)d_in[5];
    const float* Whh1  = (const float*)d_in[6];
    const float* bih1  = (const float*)d_in[7];
    const float* bhh1  = (const float*)d_in[8];
    const float* Wproj = (const float*)d_in[9];
    const float* bproj = (const float*)d_in[10];
    float* out = (float*)d_out;

    cudaFuncSetAttribute(gru_fused_kernel,
                         cudaFuncAttributeMaxDynamicSharedMemorySize, SMEM_BYTES);

    gru_fused_kernel<<<NBLOCKS, NTHREADS, SMEM_BYTES>>>(
        x, Wih0, Whh0, bih0, bhh0, Wih1, Whh1, bih1, bhh1, Wproj, bproj, out);
}